// round 2
// baseline (speedup 1.0000x reference)
#include <cuda_runtime.h>

#define BB     4
#define HH     16
#define TT     4096
#define DHH    64
#define NFF    256
#define BHH    64                      // BB*HH
#define SPLITN 16
#define ROWS_PER_BLK (TT / SPLITN)     // 256
#define NCHUNK (ROWS_PER_BLK / 64)     // 4

// Scratch (no allocation allowed in kernel_launch)
__device__ float g_pctx[(size_t)SPLITN * BHH * NFF * DHH];   // 64 MB partial contexts
__device__ float g_pksum[(size_t)SPLITN * BHH * NFF];
__device__ float g_ctx[(size_t)BHH * NFF * DHH];             // 4 MB
__device__ float g_ksum[(size_t)BHH * NFF];

#define K1_SMEM_FLOATS (64*256 + 64*256 + 64*64 + 64*64 + 64 + 64 + 256 + 256)
#define K3_SMEM_FLOATS (64*256 + 64*256 + 256*64 + 64*64 + 256 + 64 + 256 + 64)
#define K1_SMEM (K1_SMEM_FLOATS * 4)
#define K3_SMEM (K3_SMEM_FLOATS * 4)

// ---------------------------------------------------------------------------
// Kernel 1: kp = exp(ds*K@projT - dn - rowmax); partial ctx = kp^T @ V, ksum
// ---------------------------------------------------------------------------
__global__ __launch_bounds__(256, 1)
void k1_context(const float* __restrict__ kg, const float* __restrict__ vg,
                const float* __restrict__ proj) {
    extern __shared__ float sm[];
    float* projT = sm;               // [64][256]  (d-major, feature minor)
    float* kp    = projT + 64*256;   // [64][256]  dp -> kp, then ctx staging
    float* kT    = kp    + 64*256;   // [64][64]   (d-major, row minor)
    float* vs    = kT    + 64*64;    // [64][64]   (row-major)
    float* mxs   = vs    + 64*64;    // [64]
    float* dns   = mxs   + 64;       // [64]
    float* redm  = dns   + 64;       // [256]
    float* redd  = redm  + 256;      // [256]

    const int tid  = threadIdx.x;
    const int head = blockIdx.x / SPLITN;
    const int sp   = blockIdx.x % SPLITN;
    const float DS = 0.35355339059327373f;   // 64^-0.25

    // Load proj transposed into smem: projT[d][f]
    {
        const float4* pr = reinterpret_cast<const float4*>(proj + tid * 64);
        #pragma unroll
        for (int u = 0; u < 16; u++) {
            float4 p = pr[u];
            projT[(u*4+0)*256 + tid] = p.x;
            projT[(u*4+1)*256 + tid] = p.y;
            projT[(u*4+2)*256 + tid] = p.z;
            projT[(u*4+3)*256 + tid] = p.w;
        }
    }

    const int tx = tid & 31;   // phase1: feature group (8 feats) | phase2: d group
    const int ty = tid >> 5;   // phase1: row group (8 rows)      | phase2: e group
    const int lr = tid >> 2;   // loader row 0..63
    const int lp = tid & 3;    // loader quarter

    float acc2[8][8];
    #pragma unroll
    for (int i = 0; i < 8; i++)
        #pragma unroll
        for (int j = 0; j < 8; j++) acc2[i][j] = 0.f;
    float ksacc[8];
    #pragma unroll
    for (int i = 0; i < 8; i++) ksacc[i] = 0.f;

    const size_t base  = ((size_t)head * TT + (size_t)sp * ROWS_PER_BLK) * DHH;
    const float* kbase = kg + base;
    const float* vbase = vg + base;

    for (int c = 0; c < NCHUNK; c++) {
        __syncthreads();
        // Load kT (transposed) + sum-of-squares partials, and V (row-major)
        {
            const float4* kr = reinterpret_cast<const float4*>(kbase + (c*64 + lr)*64 + lp*16);
            float ss = 0.f;
            #pragma unroll
            for (int u = 0; u < 4; u++) {
                float4 kv = kr[u];
                int d0 = lp*16 + u*4;
                kT[(d0+0)*64 + lr] = kv.x;
                kT[(d0+1)*64 + lr] = kv.y;
                kT[(d0+2)*64 + lr] = kv.z;
                kT[(d0+3)*64 + lr] = kv.w;
                ss += kv.x*kv.x + kv.y*kv.y + kv.z*kv.z + kv.w*kv.w;
            }
            redd[lp*64 + lr] = ss;
            const float4* vr = reinterpret_cast<const float4*>(vbase + (c*64 + lr)*64 + lp*16);
            float4* vd = reinterpret_cast<float4*>(vs + lr*64 + lp*16);
            #pragma unroll
            for (int u = 0; u < 4; u++) vd[u] = vr[u];
        }
        __syncthreads();
        // Phase 1: dp[r][f] = ds * sum_d kT[d][r] * projT[d][f]
        {
            float accp[8][8];
            #pragma unroll
            for (int i = 0; i < 8; i++)
                #pragma unroll
                for (int j = 0; j < 8; j++) accp[i][j] = 0.f;
            const int r0 = ty*8, f0 = tx*8;
            #pragma unroll 8
            for (int d = 0; d < 64; d++) {
                float4 a0 = *reinterpret_cast<const float4*>(&kT[d*64 + r0]);
                float4 a1 = *reinterpret_cast<const float4*>(&kT[d*64 + r0 + 4]);
                float4 b0 = *reinterpret_cast<const float4*>(&projT[d*256 + f0]);
                float4 b1 = *reinterpret_cast<const float4*>(&projT[d*256 + f0 + 4]);
                float av[8] = {a0.x,a0.y,a0.z,a0.w,a1.x,a1.y,a1.z,a1.w};
                float bv[8] = {b0.x,b0.y,b0.z,b0.w,b1.x,b1.y,b1.z,b1.w};
                #pragma unroll
                for (int i = 0; i < 8; i++)
                    #pragma unroll
                    for (int j = 0; j < 8; j++)
                        accp[i][j] += av[i] * bv[j];
            }
            #pragma unroll
            for (int i = 0; i < 8; i++) {
                float4 w0 = make_float4(DS*accp[i][0], DS*accp[i][1], DS*accp[i][2], DS*accp[i][3]);
                float4 w1 = make_float4(DS*accp[i][4], DS*accp[i][5], DS*accp[i][6], DS*accp[i][7]);
                *reinterpret_cast<float4*>(&kp[(r0+i)*256 + f0])     = w0;
                *reinterpret_cast<float4*>(&kp[(r0+i)*256 + f0 + 4]) = w1;
            }
        }
        __syncthreads();
        // Row max partials
        {
            float m = -1e30f;
            const float4* row = reinterpret_cast<const float4*>(&kp[lr*256 + lp*64]);
            #pragma unroll
            for (int u = 0; u < 16; u++) {
                float4 vv = row[u];
                m = fmaxf(m, fmaxf(fmaxf(vv.x, vv.y), fmaxf(vv.z, vv.w)));
            }
            redm[lp*64 + lr] = m;
        }
        __syncthreads();
        if (tid < 64) {
            mxs[tid] = fmaxf(fmaxf(redm[tid], redm[64+tid]),
                             fmaxf(redm[128+tid], redm[192+tid]));
            dns[tid] = 0.0625f * (redd[tid] + redd[64+tid] + redd[128+tid] + redd[192+tid]);
        }
        __syncthreads();
        // exp in place: kp = exp(dp - dn - mx)
        {
            const float sub = dns[lr] + mxs[lr];
            float4* row = reinterpret_cast<float4*>(&kp[lr*256 + lp*64]);
            #pragma unroll
            for (int u = 0; u < 16; u++) {
                float4 vv = row[u];
                vv.x = __expf(vv.x - sub);
                vv.y = __expf(vv.y - sub);
                vv.z = __expf(vv.z - sub);
                vv.w = __expf(vv.w - sub);
                row[u] = vv;
            }
        }
        __syncthreads();
        // Phase 2: ctx[d][e] += kp[n][d] * v[n][e];  ksum[d] += kp[n][d]
        {
            const int d0 = tx*8, e0 = ty*8;
            #pragma unroll 4
            for (int n = 0; n < 64; n++) {
                float4 k0 = *reinterpret_cast<const float4*>(&kp[n*256 + d0]);
                float4 k1 = *reinterpret_cast<const float4*>(&kp[n*256 + d0 + 4]);
                float4 v0 = *reinterpret_cast<const float4*>(&vs[n*64 + e0]);
                float4 v1 = *reinterpret_cast<const float4*>(&vs[n*64 + e0 + 4]);
                float kv[8] = {k0.x,k0.y,k0.z,k0.w,k1.x,k1.y,k1.z,k1.w};
                float vv[8] = {v0.x,v0.y,v0.z,v0.w,v1.x,v1.y,v1.z,v1.w};
                #pragma unroll
                for (int i = 0; i < 8; i++)
                    #pragma unroll
                    for (int j = 0; j < 8; j++)
                        acc2[i][j] += kv[i] * vv[j];
                if (ty == 0) {   // warp-uniform branch: warp 0 only
                    #pragma unroll
                    for (int i = 0; i < 8; i++) ksacc[i] += kv[i];
                }
            }
        }
    }
    __syncthreads();
    // Stage ctx into smem (reuse kp area) as [d][e], then coalesced write
    {
        const int d0 = tx*8, e0 = ty*8;
        #pragma unroll
        for (int i = 0; i < 8; i++)
            #pragma unroll
            for (int j = 0; j < 8; j++)
                kp[(d0+i)*64 + (e0+j)] = acc2[i][j];
    }
    __syncthreads();
    {
        float4* dst = reinterpret_cast<float4*>(g_pctx + (size_t)(head*SPLITN + sp) * NFF * DHH);
        const float4* src = reinterpret_cast<const float4*>(kp);
        #pragma unroll
        for (int u = 0; u < 16; u++) dst[tid + u*256] = src[tid + u*256];
    }
    if (ty == 0) {
        float* dst = g_pksum + (size_t)(head*SPLITN + sp) * NFF;
        #pragma unroll
        for (int i = 0; i < 8; i++) dst[tx*8 + i] = ksacc[i];
    }
}

// ---------------------------------------------------------------------------
// Kernel 2: deterministic reduction of SPLITN partials per head
// ---------------------------------------------------------------------------
__global__ void k2_reduce() {
    const int head = blockIdx.x;
    const int tid  = threadIdx.x;
    const float4* src = reinterpret_cast<const float4*>(g_pctx + (size_t)head * SPLITN * NFF * DHH);
    float4* dst = reinterpret_cast<float4*>(g_ctx + (size_t)head * NFF * DHH);
    #pragma unroll
    for (int u = 0; u < 16; u++) {
        int idx = tid + u*256;
        float4 s = make_float4(0.f, 0.f, 0.f, 0.f);
        #pragma unroll
        for (int spp = 0; spp < SPLITN; spp++) {
            float4 p = src[(size_t)spp * (NFF*DHH/4) + idx];
            s.x += p.x; s.y += p.y; s.z += p.z; s.w += p.w;
        }
        dst[idx] = s;
    }
    float s = 0.f;
    #pragma unroll
    for (int spp = 0; spp < SPLITN; spp++)
        s += g_pksum[(size_t)(head*SPLITN + spp) * NFF + tid];
    g_ksum[(size_t)head * NFF + tid] = s;
}

// ---------------------------------------------------------------------------
// Kernel 3: qp = exp(ds*Q@projT - dn); out = (qp@ctx) / (qp@ksum)
// (query max m_q, EPS, NF^-0.5 all cancel exactly in out => omitted)
// ---------------------------------------------------------------------------
__global__ __launch_bounds__(256, 1)
void k3_out(const float* __restrict__ qg, const float* __restrict__ proj,
            float* __restrict__ outg) {
    extern __shared__ float sm[];
    float* projT = sm;               // [64][256]
    float* qp    = projT + 64*256;   // [64][256]
    float* ctx   = qp    + 64*256;   // [256][64]
    float* qT    = ctx   + 256*64;   // [64][64]
    float* ksum  = qT    + 64*64;    // [256]
    float* dns   = ksum  + 256;      // [64]
    float* redd  = dns   + 64;       // [256]
    float* dens  = redd  + 256;      // [64]

    const int tid  = threadIdx.x;
    const int head = blockIdx.x / SPLITN;
    const int sp   = blockIdx.x % SPLITN;
    const float DS = 0.35355339059327373f;

    {
        const float4* pr = reinterpret_cast<const float4*>(proj + tid * 64);
        #pragma unroll
        for (int u = 0; u < 16; u++) {
            float4 p = pr[u];
            projT[(u*4+0)*256 + tid] = p.x;
            projT[(u*4+1)*256 + tid] = p.y;
            projT[(u*4+2)*256 + tid] = p.z;
            projT[(u*4+3)*256 + tid] = p.w;
        }
    }
    {
        const float4* src = reinterpret_cast<const float4*>(g_ctx + (size_t)head * NFF * DHH);
        float4* dst = reinterpret_cast<float4*>(ctx);
        #pragma unroll
        for (int u = 0; u < 16; u++) dst[tid + u*256] = src[tid + u*256];
        ksum[tid] = g_ksum[(size_t)head * NFF + tid];
    }

    const int tx1 = tid & 31, ty1 = tid >> 5;   // phase1: 8x8 tiles
    const int tx2 = tid & 15, ty2 = tid >> 4;   // phase2: 4x4 tiles
    const int lr  = tid >> 2, lp  = tid & 3;

    const size_t base  = ((size_t)head * TT + (size_t)sp * ROWS_PER_BLK) * DHH;
    const float* qbase = qg + base;
    float* obase = outg + base;

    for (int c = 0; c < NCHUNK; c++) {
        __syncthreads();
        // Load qT transposed + sumsq partials
        {
            const float4* qr = reinterpret_cast<const float4*>(qbase + (c*64 + lr)*64 + lp*16);
            float ss = 0.f;
            #pragma unroll
            for (int u = 0; u < 4; u++) {
                float4 v = qr[u];
                int d0 = lp*16 + u*4;
                qT[(d0+0)*64 + lr] = v.x;
                qT[(d0+1)*64 + lr] = v.y;
                qT[(d0+2)*64 + lr] = v.z;
                qT[(d0+3)*64 + lr] = v.w;
                ss += v.x*v.x + v.y*v.y + v.z*v.z + v.w*v.w;
            }
            redd[lp*64 + lr] = ss;
        }
        __syncthreads();
        if (tid < 64)
            dns[tid] = 0.0625f * (redd[tid] + redd[64+tid] + redd[128+tid] + redd[192+tid]);
        __syncthreads();
        // Phase 1 + fused exp: qp[r][f] = exp(ds*dot - dn[r])
        {
            float accp[8][8];
            #pragma unroll
            for (int i = 0; i < 8; i++)
                #pragma unroll
                for (int j = 0; j < 8; j++) accp[i][j] = 0.f;
            const int r0 = ty1*8, f0 = tx1*8;
            #pragma unroll 8
            for (int d = 0; d < 64; d++) {
                float4 a0 = *reinterpret_cast<const float4*>(&qT[d*64 + r0]);
                float4 a1 = *reinterpret_cast<const float4*>(&qT[d*64 + r0 + 4]);
                float4 b0 = *reinterpret_cast<const float4*>(&projT[d*256 + f0]);
                float4 b1 = *reinterpret_cast<const float4*>(&projT[d*256 + f0 + 4]);
                float av[8] = {a0.x,a0.y,a0.z,a0.w,a1.x,a1.y,a1.z,a1.w};
                float bv[8] = {b0.x,b0.y,b0.z,b0.w,b1.x,b1.y,b1.z,b1.w};
                #pragma unroll
                for (int i = 0; i < 8; i++)
                    #pragma unroll
                    for (int j = 0; j < 8; j++)
                        accp[i][j] += av[i] * bv[j];
            }
            #pragma unroll
            for (int i = 0; i < 8; i++) {
                float dnr = dns[r0 + i];
                float4 w0 = make_float4(__expf(DS*accp[i][0]-dnr), __expf(DS*accp[i][1]-dnr),
                                        __expf(DS*accp[i][2]-dnr), __expf(DS*accp[i][3]-dnr));
                float4 w1 = make_float4(__expf(DS*accp[i][4]-dnr), __expf(DS*accp[i][5]-dnr),
                                        __expf(DS*accp[i][6]-dnr), __expf(DS*accp[i][7]-dnr));
                *reinterpret_cast<float4*>(&qp[(r0+i)*256 + f0])     = w0;
                *reinterpret_cast<float4*>(&qp[(r0+i)*256 + f0 + 4]) = w1;
            }
        }
        __syncthreads();
        // Denominator partials: den[r] = sum_d qp[r][d]*ksum[d]
        {
            float s = 0.f;
            const float4* row = reinterpret_cast<const float4*>(&qp[lr*256 + lp*64]);
            const float4* ks4 = reinterpret_cast<const float4*>(&ksum[lp*64]);
            #pragma unroll
            for (int u = 0; u < 16; u++) {
                float4 a = row[u], b = ks4[u];
                s += a.x*b.x + a.y*b.y + a.z*b.z + a.w*b.w;
            }
            redd[lp*64 + lr] = s;
        }
        __syncthreads();
        if (tid < 64)
            dens[tid] = redd[tid] + redd[64+tid] + redd[128+tid] + redd[192+tid];
        __syncthreads();
        // Phase 2: out[r][e] = (sum_d qp[r][d]*ctx[d][e]) / dens[r]
        {
            const int r0 = ty2*4, e0 = tx2*4;
            float acc[4][4];
            #pragma unroll
            for (int i = 0; i < 4; i++)
                #pragma unroll
                for (int j = 0; j < 4; j++) acc[i][j] = 0.f;
            #pragma unroll 4
            for (int d4 = 0; d4 < 64; d4++) {
                float4 q0 = *reinterpret_cast<const float4*>(&qp[(r0+0)*256 + d4*4]);
                float4 q1 = *reinterpret_cast<const float4*>(&qp[(r0+1)*256 + d4*4]);
                float4 q2 = *reinterpret_cast<const float4*>(&qp[(r0+2)*256 + d4*4]);
                float4 q3 = *reinterpret_cast<const float4*>(&qp[(r0+3)*256 + d4*4]);
                float4 c0 = *reinterpret_cast<const float4*>(&ctx[(d4*4+0)*64 + e0]);
                float4 c1 = *reinterpret_cast<const float4*>(&ctx[(d4*4+1)*64 + e0]);
                float4 c2 = *reinterpret_cast<const float4*>(&ctx[(d4*4+2)*64 + e0]);
                float4 c3 = *reinterpret_cast<const float4*>(&ctx[(d4*4+3)*64 + e0]);
                float qv[4][4] = {{q0.x,q0.y,q0.z,q0.w},{q1.x,q1.y,q1.z,q1.w},
                                  {q2.x,q2.y,q2.z,q2.w},{q3.x,q3.y,q3.z,q3.w}};
                float cv[4][4] = {{c0.x,c0.y,c0.z,c0.w},{c1.x,c1.y,c1.z,c1.w},
                                  {c2.x,c2.y,c2.z,c2.w},{c3.x,c3.y,c3.z,c3.w}};
                #pragma unroll
                for (int i = 0; i < 4; i++)
                    #pragma unroll
                    for (int j = 0; j < 4; j++)
                        acc[i][j] += qv[i][0]*cv[0][j] + qv[i][1]*cv[1][j]
                                   + qv[i][2]*cv[2][j] + qv[i][3]*cv[3][j];
            }
            #pragma unroll
            for (int i = 0; i < 4; i++) {
                float rinv = 1.0f / dens[r0 + i];
                float4 w = make_float4(acc[i][0]*rinv, acc[i][1]*rinv,
                                       acc[i][2]*rinv, acc[i][3]*rinv);
                *reinterpret_cast<float4*>(&obase[(size_t)(c*64 + r0 + i)*64 + e0]) = w;
            }
        }
    }
}

extern "C" void kernel_launch(void* const* d_in, const int* in_sizes, int n_in,
                              void* d_out, int out_size) {
    const float* q    = (const float*)d_in[0];
    const float* k    = (const float*)d_in[1];
    const float* v    = (const float*)d_in[2];
    const float* proj = (const float*)d_in[3];
    float* out        = (float*)d_out;

    cudaFuncSetAttribute(k1_context, cudaFuncAttributeMaxDynamicSharedMemorySize, K1_SMEM);
    cudaFuncSetAttribute(k3_out,     cudaFuncAttributeMaxDynamicSharedMemorySize, K3_SMEM);

    k1_context<<<BHH * SPLITN, 256, K1_SMEM>>>(k, v, proj);
    k2_reduce<<<BHH, 256>>>();
    k3_out<<<BHH * SPLITN, 256, K3_SMEM>>>(q, proj, out);
}

// round 3
// speedup vs baseline: 1.0187x; 1.0187x over previous
#include <cuda_runtime.h>

#define BB     4
#define HH     16
#define TT     4096
#define DHH    64
#define NFF    256
#define BHH    64                      // BB*HH
#define SPLITN 16
#define ROWS_PER_BLK (TT / SPLITN)     // 256
#define NCHUNK (ROWS_PER_BLK / 64)     // 4

typedef unsigned long long u64;

__device__ __forceinline__ u64 pack2(float x) {
    u64 r; asm("mov.b64 %0, {%1, %1};" : "=l"(r) : "f"(x)); return r;
}
__device__ __forceinline__ u64 fma2(u64 a, u64 b, u64 c) {
    u64 d; asm("fma.rn.f32x2 %0, %1, %2, %3;" : "=l"(d) : "l"(a), "l"(b), "l"(c)); return d;
}
__device__ __forceinline__ u64 mul2(u64 a, u64 b) {
    u64 d; asm("mul.rn.f32x2 %0, %1, %2;" : "=l"(d) : "l"(a), "l"(b)); return d;
}
__device__ __forceinline__ float2 unpk2(u64 a) {
    float2 f; asm("mov.b64 {%0, %1}, %2;" : "=f"(f.x), "=f"(f.y) : "l"(a)); return f;
}

// Scratch (no allocation allowed in kernel_launch)
__device__ float g_pctx[(size_t)SPLITN * BHH * NFF * DHH];   // 64 MB partial contexts
__device__ float g_pksum[(size_t)SPLITN * BHH * NFF];
__device__ float g_ctx[(size_t)BHH * NFF * DHH];             // 4 MB
__device__ float g_ksum[(size_t)BHH * NFF];

#define K1_SMEM_FLOATS (64*256 + 64*256 + 64*64 + 64*64 + 64 + 64 + 256 + 256)
#define K3_SMEM_FLOATS (64*256 + 64*256 + 256*64 + 64*64 + 256 + 64 + 256 + 64)
#define K1_SMEM (K1_SMEM_FLOATS * 4)
#define K3_SMEM (K3_SMEM_FLOATS * 4)

// ---------------------------------------------------------------------------
// Kernel 1: kp = exp(ds*K@projT - dn - rowmax); partial ctx = kp^T @ V, ksum
// ---------------------------------------------------------------------------
__global__ __launch_bounds__(256, 1)
void k1_context(const float* __restrict__ kg, const float* __restrict__ vg,
                const float* __restrict__ proj) {
    extern __shared__ float sm[];
    float* projT = sm;               // [64][256]  (d-major, feature minor)
    float* kp    = projT + 64*256;   // [64][256]  dp -> kp, then ctx staging
    float* kT    = kp    + 64*256;   // [64][64]   (d-major, row minor)
    float* vs    = kT    + 64*64;    // [64][64]   (row-major)
    float* mxs   = vs    + 64*64;    // [64]
    float* dns   = mxs   + 64;       // [64]
    float* redm  = dns   + 64;       // [256]
    float* redd  = redm  + 256;      // [256]

    const int tid  = threadIdx.x;
    const int head = blockIdx.x / SPLITN;
    const int sp   = blockIdx.x % SPLITN;
    const float DS = 0.35355339059327373f;   // 64^-0.25
    const u64 ds2  = pack2(DS);

    // Load proj transposed into smem: projT[d][f]
    {
        const float4* pr = reinterpret_cast<const float4*>(proj + tid * 64);
        #pragma unroll
        for (int u = 0; u < 16; u++) {
            float4 p = pr[u];
            projT[(u*4+0)*256 + tid] = p.x;
            projT[(u*4+1)*256 + tid] = p.y;
            projT[(u*4+2)*256 + tid] = p.z;
            projT[(u*4+3)*256 + tid] = p.w;
        }
    }

    const int tx = tid & 31;   // phase1: feature group (8 feats) | phase2: d group
    const int ty = tid >> 5;   // phase1: row group (8 rows)      | phase2: e group
    const int lr = tid >> 2;   // loader row 0..63
    const int lp = tid & 3;    // loader quarter

    u64 acc2[8][4];            // [d-idx][e-pair]
    #pragma unroll
    for (int i = 0; i < 8; i++)
        #pragma unroll
        for (int j = 0; j < 4; j++) acc2[i][j] = 0ULL;
    float ksacc[8];
    #pragma unroll
    for (int i = 0; i < 8; i++) ksacc[i] = 0.f;

    const size_t base  = ((size_t)head * TT + (size_t)sp * ROWS_PER_BLK) * DHH;
    const float* kbase = kg + base;
    const float* vbase = vg + base;

    for (int c = 0; c < NCHUNK; c++) {
        __syncthreads();
        // Load kT (transposed) + sum-of-squares partials, and V (row-major)
        {
            const float4* kr = reinterpret_cast<const float4*>(kbase + (c*64 + lr)*64 + lp*16);
            float ss = 0.f;
            #pragma unroll
            for (int u = 0; u < 4; u++) {
                float4 kv = kr[u];
                int d0 = lp*16 + u*4;
                kT[(d0+0)*64 + lr] = kv.x;
                kT[(d0+1)*64 + lr] = kv.y;
                kT[(d0+2)*64 + lr] = kv.z;
                kT[(d0+3)*64 + lr] = kv.w;
                ss += kv.x*kv.x + kv.y*kv.y + kv.z*kv.z + kv.w*kv.w;
            }
            redd[lp*64 + lr] = ss;
            const float4* vr = reinterpret_cast<const float4*>(vbase + (c*64 + lr)*64 + lp*16);
            float4* vd = reinterpret_cast<float4*>(vs + lr*64 + lp*16);
            #pragma unroll
            for (int u = 0; u < 4; u++) vd[u] = vr[u];
        }
        __syncthreads();
        // Phase 1: dp[r][f] = ds * sum_d kT[d][r] * projT[d][f]  (f32x2 on f-pairs)
        {
            u64 accp[8][4];
            #pragma unroll
            for (int i = 0; i < 8; i++)
                #pragma unroll
                for (int j = 0; j < 4; j++) accp[i][j] = 0ULL;
            const int r0 = ty*8, f0 = tx*8;
            #pragma unroll 8
            for (int d = 0; d < 64; d++) {
                float4 a0 = *reinterpret_cast<const float4*>(&kT[d*64 + r0]);
                float4 a1 = *reinterpret_cast<const float4*>(&kT[d*64 + r0 + 4]);
                ulonglong2 b0 = *reinterpret_cast<const ulonglong2*>(&projT[d*256 + f0]);
                ulonglong2 b1 = *reinterpret_cast<const ulonglong2*>(&projT[d*256 + f0 + 4]);
                u64 ap[8] = {pack2(a0.x),pack2(a0.y),pack2(a0.z),pack2(a0.w),
                             pack2(a1.x),pack2(a1.y),pack2(a1.z),pack2(a1.w)};
                u64 bp[4] = {b0.x, b0.y, b1.x, b1.y};
                #pragma unroll
                for (int i = 0; i < 8; i++)
                    #pragma unroll
                    for (int j = 0; j < 4; j++)
                        accp[i][j] = fma2(ap[i], bp[j], accp[i][j]);
            }
            #pragma unroll
            for (int i = 0; i < 8; i++) {
                ulonglong2 w0, w1;
                w0.x = mul2(accp[i][0], ds2); w0.y = mul2(accp[i][1], ds2);
                w1.x = mul2(accp[i][2], ds2); w1.y = mul2(accp[i][3], ds2);
                *reinterpret_cast<ulonglong2*>(&kp[(r0+i)*256 + f0])     = w0;
                *reinterpret_cast<ulonglong2*>(&kp[(r0+i)*256 + f0 + 4]) = w1;
            }
        }
        __syncthreads();
        // Row max partials
        {
            float m = -1e30f;
            const float4* row = reinterpret_cast<const float4*>(&kp[lr*256 + lp*64]);
            #pragma unroll
            for (int u = 0; u < 16; u++) {
                float4 vv = row[u];
                m = fmaxf(m, fmaxf(fmaxf(vv.x, vv.y), fmaxf(vv.z, vv.w)));
            }
            redm[lp*64 + lr] = m;
        }
        __syncthreads();
        if (tid < 64) {
            mxs[tid] = fmaxf(fmaxf(redm[tid], redm[64+tid]),
                             fmaxf(redm[128+tid], redm[192+tid]));
            dns[tid] = 0.0625f * (redd[tid] + redd[64+tid] + redd[128+tid] + redd[192+tid]);
        }
        __syncthreads();
        // exp in place: kp = exp(dp - dn - mx)
        {
            const float sub = dns[lr] + mxs[lr];
            float4* row = reinterpret_cast<float4*>(&kp[lr*256 + lp*64]);
            #pragma unroll
            for (int u = 0; u < 16; u++) {
                float4 vv = row[u];
                vv.x = __expf(vv.x - sub);
                vv.y = __expf(vv.y - sub);
                vv.z = __expf(vv.z - sub);
                vv.w = __expf(vv.w - sub);
                row[u] = vv;
            }
        }
        __syncthreads();
        // Phase 2: ctx[d][e] += kp[n][d] * v[n][e]  (f32x2 on e-pairs); ksum[d] += kp[n][d]
        {
            const int d0 = tx*8, e0 = ty*8;
            #pragma unroll 4
            for (int n = 0; n < 64; n++) {
                float4 k0 = *reinterpret_cast<const float4*>(&kp[n*256 + d0]);
                float4 k1 = *reinterpret_cast<const float4*>(&kp[n*256 + d0 + 4]);
                ulonglong2 v0 = *reinterpret_cast<const ulonglong2*>(&vs[n*64 + e0]);
                ulonglong2 v1 = *reinterpret_cast<const ulonglong2*>(&vs[n*64 + e0 + 4]);
                float kv[8] = {k0.x,k0.y,k0.z,k0.w,k1.x,k1.y,k1.z,k1.w};
                u64 kq[8] = {pack2(k0.x),pack2(k0.y),pack2(k0.z),pack2(k0.w),
                             pack2(k1.x),pack2(k1.y),pack2(k1.z),pack2(k1.w)};
                u64 vp[4] = {v0.x, v0.y, v1.x, v1.y};
                #pragma unroll
                for (int i = 0; i < 8; i++)
                    #pragma unroll
                    for (int j = 0; j < 4; j++)
                        acc2[i][j] = fma2(kq[i], vp[j], acc2[i][j]);
                if (ty == 0) {   // warp-uniform branch: warp 0 only
                    #pragma unroll
                    for (int i = 0; i < 8; i++) ksacc[i] += kv[i];
                }
            }
        }
    }
    __syncthreads();
    // Stage ctx into smem (reuse kp area) as [d][e], then coalesced write
    {
        const int d0 = tx*8, e0 = ty*8;
        #pragma unroll
        for (int i = 0; i < 8; i++)
            #pragma unroll
            for (int j = 0; j < 4; j++)
                *reinterpret_cast<u64*>(&kp[(d0+i)*64 + e0 + j*2]) = acc2[i][j];
    }
    __syncthreads();
    {
        float4* dst = reinterpret_cast<float4*>(g_pctx + (size_t)(head*SPLITN + sp) * NFF * DHH);
        const float4* src = reinterpret_cast<const float4*>(kp);
        #pragma unroll
        for (int u = 0; u < 16; u++) dst[tid + u*256] = src[tid + u*256];
    }
    if (ty == 0) {
        float* dst = g_pksum + (size_t)(head*SPLITN + sp) * NFF;
        #pragma unroll
        for (int i = 0; i < 8; i++) dst[tx*8 + i] = ksacc[i];
    }
}

// ---------------------------------------------------------------------------
// Kernel 2: deterministic reduction of SPLITN partials per head
// ---------------------------------------------------------------------------
__global__ void k2_reduce() {
    const int head = blockIdx.x;
    const int tid  = threadIdx.x;
    const float4* src = reinterpret_cast<const float4*>(g_pctx + (size_t)head * SPLITN * NFF * DHH);
    float4* dst = reinterpret_cast<float4*>(g_ctx + (size_t)head * NFF * DHH);
    #pragma unroll
    for (int u = 0; u < 16; u++) {
        int idx = tid + u*256;
        float4 s = make_float4(0.f, 0.f, 0.f, 0.f);
        #pragma unroll
        for (int spp = 0; spp < SPLITN; spp++) {
            float4 p = src[(size_t)spp * (NFF*DHH/4) + idx];
            s.x += p.x; s.y += p.y; s.z += p.z; s.w += p.w;
        }
        dst[idx] = s;
    }
    float s = 0.f;
    #pragma unroll
    for (int spp = 0; spp < SPLITN; spp++)
        s += g_pksum[(size_t)(head*SPLITN + spp) * NFF + tid];
    g_ksum[(size_t)head * NFF + tid] = s;
}

// ---------------------------------------------------------------------------
// Kernel 3: qp = exp(ds*Q@projT - dn); out = (qp@ctx) / (qp@ksum)
// (query max m_q, EPS, NF^-0.5 all cancel exactly in out => omitted)
// ---------------------------------------------------------------------------
__global__ __launch_bounds__(256, 1)
void k3_out(const float* __restrict__ qg, const float* __restrict__ proj,
            float* __restrict__ outg) {
    extern __shared__ float sm[];
    float* projT = sm;               // [64][256]
    float* qp    = projT + 64*256;   // [64][256]
    float* ctx   = qp    + 64*256;   // [256][64]
    float* qT    = ctx   + 256*64;   // [64][64]
    float* ksum  = qT    + 64*64;    // [256]
    float* dns   = ksum  + 256;      // [64]
    float* redd  = dns   + 64;       // [256]
    float* dens  = redd  + 256;      // [64]

    const int tid  = threadIdx.x;
    const int head = blockIdx.x / SPLITN;
    const int sp   = blockIdx.x % SPLITN;
    const float DS = 0.35355339059327373f;

    {
        const float4* pr = reinterpret_cast<const float4*>(proj + tid * 64);
        #pragma unroll
        for (int u = 0; u < 16; u++) {
            float4 p = pr[u];
            projT[(u*4+0)*256 + tid] = p.x;
            projT[(u*4+1)*256 + tid] = p.y;
            projT[(u*4+2)*256 + tid] = p.z;
            projT[(u*4+3)*256 + tid] = p.w;
        }
    }
    {
        const float4* src = reinterpret_cast<const float4*>(g_ctx + (size_t)head * NFF * DHH);
        float4* dst = reinterpret_cast<float4*>(ctx);
        #pragma unroll
        for (int u = 0; u < 16; u++) dst[tid + u*256] = src[tid + u*256];
        ksum[tid] = g_ksum[(size_t)head * NFF + tid];
    }

    const int tx1 = tid & 31, ty1 = tid >> 5;   // phase1: 8x8 tiles
    const int tx2 = tid & 15, ty2 = tid >> 4;   // phase2: 4x4 tiles
    const int lr  = tid >> 2, lp  = tid & 3;

    const size_t base  = ((size_t)head * TT + (size_t)sp * ROWS_PER_BLK) * DHH;
    const float* qbase = qg + base;
    float* obase = outg + base;

    for (int c = 0; c < NCHUNK; c++) {
        __syncthreads();
        // Load qT transposed + sumsq partials
        {
            const float4* qr = reinterpret_cast<const float4*>(qbase + (c*64 + lr)*64 + lp*16);
            float ss = 0.f;
            #pragma unroll
            for (int u = 0; u < 4; u++) {
                float4 v = qr[u];
                int d0 = lp*16 + u*4;
                qT[(d0+0)*64 + lr] = v.x;
                qT[(d0+1)*64 + lr] = v.y;
                qT[(d0+2)*64 + lr] = v.z;
                qT[(d0+3)*64 + lr] = v.w;
                ss += v.x*v.x + v.y*v.y + v.z*v.z + v.w*v.w;
            }
            redd[lp*64 + lr] = ss;
        }
        __syncthreads();
        if (tid < 64)
            dns[tid] = 0.0625f * (redd[tid] + redd[64+tid] + redd[128+tid] + redd[192+tid]);
        __syncthreads();
        // Phase 1 + fused exp: qp[r][f] = exp(ds*dot - dn[r])  (f32x2 accumulate)
        {
            u64 accp[8][4];
            #pragma unroll
            for (int i = 0; i < 8; i++)
                #pragma unroll
                for (int j = 0; j < 4; j++) accp[i][j] = 0ULL;
            const int r0 = ty1*8, f0 = tx1*8;
            #pragma unroll 8
            for (int d = 0; d < 64; d++) {
                float4 a0 = *reinterpret_cast<const float4*>(&qT[d*64 + r0]);
                float4 a1 = *reinterpret_cast<const float4*>(&qT[d*64 + r0 + 4]);
                ulonglong2 b0 = *reinterpret_cast<const ulonglong2*>(&projT[d*256 + f0]);
                ulonglong2 b1 = *reinterpret_cast<const ulonglong2*>(&projT[d*256 + f0 + 4]);
                u64 ap[8] = {pack2(a0.x),pack2(a0.y),pack2(a0.z),pack2(a0.w),
                             pack2(a1.x),pack2(a1.y),pack2(a1.z),pack2(a1.w)};
                u64 bp[4] = {b0.x, b0.y, b1.x, b1.y};
                #pragma unroll
                for (int i = 0; i < 8; i++)
                    #pragma unroll
                    for (int j = 0; j < 4; j++)
                        accp[i][j] = fma2(ap[i], bp[j], accp[i][j]);
            }
            #pragma unroll
            for (int i = 0; i < 8; i++) {
                float dnr = dns[r0 + i];
                float2 p0 = unpk2(accp[i][0]);
                float2 p1 = unpk2(accp[i][1]);
                float2 p2 = unpk2(accp[i][2]);
                float2 p3 = unpk2(accp[i][3]);
                float4 w0 = make_float4(__expf(DS*p0.x-dnr), __expf(DS*p0.y-dnr),
                                        __expf(DS*p1.x-dnr), __expf(DS*p1.y-dnr));
                float4 w1 = make_float4(__expf(DS*p2.x-dnr), __expf(DS*p2.y-dnr),
                                        __expf(DS*p3.x-dnr), __expf(DS*p3.y-dnr));
                *reinterpret_cast<float4*>(&qp[(r0+i)*256 + f0])     = w0;
                *reinterpret_cast<float4*>(&qp[(r0+i)*256 + f0 + 4]) = w1;
            }
        }
        __syncthreads();
        // Denominator partials: den[r] = sum_d qp[r][d]*ksum[d]
        {
            float s = 0.f;
            const float4* row = reinterpret_cast<const float4*>(&qp[lr*256 + lp*64]);
            const float4* ks4 = reinterpret_cast<const float4*>(&ksum[lp*64]);
            #pragma unroll
            for (int u = 0; u < 16; u++) {
                float4 a = row[u], b = ks4[u];
                s += a.x*b.x + a.y*b.y + a.z*b.z + a.w*b.w;
            }
            redd[lp*64 + lr] = s;
        }
        __syncthreads();
        if (tid < 64)
            dens[tid] = redd[tid] + redd[64+tid] + redd[128+tid] + redd[192+tid];
        __syncthreads();
        // Phase 2: out[r][e] = (sum_d qp[r][d]*ctx[d][e]) / dens[r]  (f32x2 on e-pairs)
        {
            const int r0 = ty2*4, e0 = tx2*4;
            u64 acc[4][2];
            #pragma unroll
            for (int i = 0; i < 4; i++) { acc[i][0] = 0ULL; acc[i][1] = 0ULL; }
            #pragma unroll 4
            for (int d4 = 0; d4 < 64; d4++) {
                float4 q0 = *reinterpret_cast<const float4*>(&qp[(r0+0)*256 + d4*4]);
                float4 q1 = *reinterpret_cast<const float4*>(&qp[(r0+1)*256 + d4*4]);
                float4 q2 = *reinterpret_cast<const float4*>(&qp[(r0+2)*256 + d4*4]);
                float4 q3 = *reinterpret_cast<const float4*>(&qp[(r0+3)*256 + d4*4]);
                float qv[4][4] = {{q0.x,q0.y,q0.z,q0.w},{q1.x,q1.y,q1.z,q1.w},
                                  {q2.x,q2.y,q2.z,q2.w},{q3.x,q3.y,q3.z,q3.w}};
                #pragma unroll
                for (int dd = 0; dd < 4; dd++) {
                    ulonglong2 cb = *reinterpret_cast<const ulonglong2*>(&ctx[(d4*4+dd)*64 + e0]);
                    #pragma unroll
                    for (int i = 0; i < 4; i++) {
                        u64 qd = pack2(qv[i][dd]);
                        acc[i][0] = fma2(qd, cb.x, acc[i][0]);
                        acc[i][1] = fma2(qd, cb.y, acc[i][1]);
                    }
                }
            }
            #pragma unroll
            for (int i = 0; i < 4; i++) {
                float rinv = 1.0f / dens[r0 + i];
                float2 a0 = unpk2(acc[i][0]);
                float2 a1 = unpk2(acc[i][1]);
                float4 w = make_float4(a0.x*rinv, a0.y*rinv, a1.x*rinv, a1.y*rinv);
                *reinterpret_cast<float4*>(&obase[(size_t)(c*64 + r0 + i)*64 + e0]) = w;
            }
        }
    }
}

extern "C" void kernel_launch(void* const* d_in, const int* in_sizes, int n_in,
                              void* d_out, int out_size) {
    const float* q    = (const float*)d_in[0];
    const float* k    = (const float*)d_in[1];
    const float* v    = (const float*)d_in[2];
    const float* proj = (const float*)d_in[3];
    float* out        = (float*)d_out;

    cudaFuncSetAttribute(k1_context, cudaFuncAttributeMaxDynamicSharedMemorySize, K1_SMEM);
    cudaFuncSetAttribute(k3_out,     cudaFuncAttributeMaxDynamicSharedMemorySize, K3_SMEM);

    k1_context<<<BHH * SPLITN, 256, K1_SMEM>>>(k, v, proj);
    k2_reduce<<<BHH, 256>>>();
    k3_out<<<BHH * SPLITN, 256, K3_SMEM>>>(q, proj, out);
}